// round 4
// baseline (speedup 1.0000x reference)
#include <cuda_runtime.h>
#include <cuda_bf16.h>
#include <math.h>

// Problem constants (fixed shapes from the reference)
constexpr int Bc = 64;
constexpr int Tc = 2048;
constexpr int Vc = 256;
constexpr int Uc = 256;
constexpr int Sc = 2 * Uc + 1;   // 513 CTC extended states
constexpr int Rr = 16;           // cp.async row ring depth (power of 2)
#define NEGV (-1e30f)

// Scratch (no cudaMalloc allowed)
__device__ float g_logZ[Bc * Tc];
__device__ float g_scores[Bc];

// ---------------- cp.async helpers ----------------
#define CP_ASYNC_16(dst_smem_u32, src_ptr)                                 \
    asm volatile("cp.async.cg.shared.global [%0], [%1], 16;\n" ::          \
                     "r"(dst_smem_u32), "l"(src_ptr))
#define CP_COMMIT() asm volatile("cp.async.commit_group;\n" ::: "memory")
#define CP_WAIT(n) asm volatile("cp.async.wait_group %0;\n" ::"n"(n) : "memory")

// ---------------- Kernel 1: logZ[b,t] = logsumexp over V ----------------
// One warp per (b,t) row of 256 floats. Pure HBM streaming.
__global__ void __launch_bounds__(256) logz_kernel(const float* __restrict__ logits) {
    int gw = (blockIdx.x * blockDim.x + threadIdx.x) >> 5;
    int lane = threadIdx.x & 31;
    if (gw >= Bc * Tc) return;
    const float4* row = reinterpret_cast<const float4*>(logits + (size_t)gw * Vc);
    float4 x0 = row[lane];
    float4 x1 = row[lane + 32];
    float m = fmaxf(fmaxf(fmaxf(x0.x, x0.y), fmaxf(x0.z, x0.w)),
                    fmaxf(fmaxf(x1.x, x1.y), fmaxf(x1.z, x1.w)));
#pragma unroll
    for (int o = 16; o; o >>= 1) m = fmaxf(m, __shfl_xor_sync(0xFFFFFFFFu, m, o));
    float s = expf(x0.x - m) + expf(x0.y - m) + expf(x0.z - m) + expf(x0.w - m) +
              expf(x1.x - m) + expf(x1.y - m) + expf(x1.z - m) + expf(x1.w - m);
#pragma unroll
    for (int o = 16; o; o >>= 1) s += __shfl_xor_sync(0xFFFFFFFFu, s, o);
    if (lane == 0) g_logZ[gw] = m + logf(s);
}

// ---------------- Kernel 2: Viterbi DP over raw logits ----------------
// One block per batch element. 544 threads; thread s owns state s (< 513).
// alpha is double-buffered in shared with 2 NEG sentinels at the front so
// s-1 / s-2 reads need no branches. Logits rows are streamed through a
// 16-deep cp.async ring; effective prefetch distance = 15 iterations.
__global__ void __launch_bounds__(544, 1)
dp_kernel(const float* __restrict__ logits,
          const int* __restrict__ targets,
          const int* __restrict__ loglens,
          const int* __restrict__ tgtlens) {
    __shared__ float rowbuf[Rr][Vc];      // 16 KB
    __shared__ float abuf[2][Sc + 2];     // double-buffered alpha (+2 sentinels)
    __shared__ float res_pair[2];         // [0]=alpha[idx_blank], [1]=alpha[idx_label] at t=len-1

    const int b = blockIdx.x;
    const int tid = threadIdx.x;
    const int s = tid;
    const int len = loglens[b];           // in [T/2, T]
    const int ul = tgtlens[b];            // in [U/2, U]
    const int idxb = 2 * ul;              // last blank state
    const int idxl = 2 * ul - 1;          // last label state

    // Per-state constants (time-invariant)
    int my_ext = 0;                        // vocab index emitted by state s
    bool my_skip = false;                  // s-2 transition allowed
    bool my_valid = false;                 // state within 2*ul+1
    if (s < Sc) {
        my_valid = (s <= idxb);
        if (s & 1) {
            my_ext = targets[b * Uc + (s >> 1)];
            my_skip = (s >= 2) && (my_ext != targets[b * Uc + (s >> 1) - 1]);
        }
    }
    if (tid < 2) {
        abuf[0][tid] = NEGV;
        abuf[1][tid] = NEGV;
    }

    const float* base = logits + ((size_t)b * Tc) * Vc;

    // Prologue: prefetch rows 0 .. Rr-2 (Rr-1 groups outstanding)
    if (tid < 64) {
#pragma unroll
        for (int j = 0; j < Rr - 1; ++j) {
            unsigned dst = (unsigned)__cvta_generic_to_shared(&rowbuf[j][tid * 4]);
            CP_ASYNC_16(dst, base + (size_t)j * Vc + tid * 4);
            CP_COMMIT();
        }
    }

    int p = 0;
    for (int t = 0; t < Tc; ++t) {
        // Row t guaranteed complete once at most Rr-2 groups remain pending.
        if (tid < 64) CP_WAIT(Rr - 2);
        __syncthreads();  // row t visible to all; previous alpha writes visible;
                          // slot (t-1)&15 now free for refill.
        if (tid < 64) {
            int tn = t + Rr - 1;
            if (tn < Tc) {
                unsigned dst =
                    (unsigned)__cvta_generic_to_shared(&rowbuf[tn & (Rr - 1)][tid * 4]);
                CP_ASYNC_16(dst, base + (size_t)tn * Vc + tid * 4);
            }
            CP_COMMIT();  // always commit (possibly empty) to keep group count stable
        }
        if (s < Sc) {
            float em = rowbuf[t & (Rr - 1)][my_ext];  // raw logit (logZ folded in later)
            float v;
            if (t == 0) {
                v = (my_valid && s <= 1) ? em : NEGV;
            } else {
                float a0 = abuf[p][s + 2];
                float a1 = abuf[p][s + 1];
                float a2 = my_skip ? abuf[p][s] : NEGV;
                v = my_valid ? fmaxf(a0, fmaxf(a1, a2)) + em : NEGV;
            }
            abuf[p ^ 1][s + 2] = v;
            if (t == len - 1) {
                if (s == idxb) res_pair[0] = v;
                if (s == idxl) res_pair[1] = v;
            }
        }
        p ^= 1;
    }
    __syncthreads();
    if (tid == 0) g_scores[b] = fmaxf(res_pair[0], res_pair[1]);
}

// ---------------- Kernel 3: deterministic finalize ----------------
// loss = sum_b ( sum_{t<len_b} logZ[b,t] - viterbi_score_b ) / sum_b len_b
__global__ void __launch_bounds__(1024) finalize_kernel(const int* __restrict__ loglens,
                                                        float* __restrict__ out) {
    __shared__ float partial[Bc];
    int w = threadIdx.x >> 5;
    int lane = threadIdx.x & 31;
    for (int b = w; b < Bc; b += 32) {
        int len = loglens[b];
        float acc = 0.f;
        for (int t = lane; t < Tc; t += 32) {
            if (t < len) acc += g_logZ[b * Tc + t];
        }
#pragma unroll
        for (int o = 16; o; o >>= 1) acc += __shfl_down_sync(0xFFFFFFFFu, acc, o);
        if (lane == 0) partial[b] = acc - g_scores[b];
    }
    __syncthreads();
    if (threadIdx.x == 0) {
        float num = 0.f, den = 0.f;
        for (int b = 0; b < Bc; ++b) {
            num += partial[b];
            den += (float)loglens[b];
        }
        out[0] = num / den;
    }
}

extern "C" void kernel_launch(void* const* d_in, const int* in_sizes, int n_in,
                              void* d_out, int out_size) {
    const float* logits = (const float*)d_in[0];
    const int* targets = (const int*)d_in[1];
    const int* loglens = (const int*)d_in[2];
    const int* tgtlens = (const int*)d_in[3];
    float* out = (float*)d_out;

    logz_kernel<<<(Bc * Tc) / 8, 256>>>(logits);
    dp_kernel<<<Bc, 544>>>(logits, targets, loglens, tgtlens);
    finalize_kernel<<<1, 1024>>>(loglens, out);
}

// round 5
// speedup vs baseline: 1.5809x; 1.5809x over previous
#include <cuda_runtime.h>
#include <cuda_bf16.h>
#include <math.h>

// Shapes fixed by the reference
constexpr int Bc = 64;
constexpr int Tc = 2048;
constexpr int Vc = 256;
constexpr int Uc = 256;
#define NEGV (-1e30f)

// per-batch partial: sum_{t<len} logZ  -  viterbi raw score
__device__ float g_partial[Bc];

#define CP_ASYNC_16(dst, src)                                              \
    asm volatile("cp.async.cg.shared.global [%0], [%1], 16;\n" ::          \
                     "r"(dst), "l"(src))
#define CP_COMMIT() asm volatile("cp.async.commit_group;\n" ::: "memory")
#define CP_WAIT(n) asm volatile("cp.async.wait_group %0;\n" ::"n"(n) : "memory")

constexpr int CHUNK = 8;   // rows (timesteps) per cp.async group
constexpr int NCH = 4;     // ring chunks (32 rows = 32 KB)
constexpr int PREF = 3;    // chunks in flight

// One block per batch. Warps 0-1: Viterbi DP over 513 states in registers
// (8 states/thread, +1 extra state 512 on warp1 lane31). Warps 2-7: per-row
// logsumexp of the staged logits rows. 8 DP steps per __syncthreads.
__global__ void __launch_bounds__(256, 1)
dp_kernel(const float* __restrict__ logits,
          const int* __restrict__ targets,
          const int* __restrict__ loglens,
          const int* __restrict__ tgtlens) {
    __shared__ float ring[NCH * CHUNK][Vc];  // 32 KB
    __shared__ float sh_halo[2][16];         // warp0 top-16 alpha, double-buffered
    __shared__ float sh_lz[6];
    __shared__ float sh_pair[2];

    const int b = blockIdx.x;
    const int tid = threadIdx.x;
    const int w = tid >> 5, lane = tid & 31;
    const int len = loglens[b];
    const int ul = tgtlens[b];
    const int idxb = 2 * ul;        // last blank state
    const int idxl = 2 * ul - 1;    // last label state
    const int lenm1 = len - 1;
    const int ngroups = (len + 7) >> 3;

    const float* base = logits + (size_t)b * Tc * Vc;

    if (tid < 16) { sh_halo[0][tid] = NEGV; sh_halo[1][tid] = NEGV; }
    if (tid < 2) sh_pair[tid] = NEGV;

    // prologue: prefetch chunks 0..PREF-1 (each chunk = contiguous 8 KB)
    {
        const char* cb = (const char*)base;
        char* rb = (char*)&ring[0][0];
#pragma unroll
        for (int c = 0; c < PREF; ++c) {
            unsigned d0 = (unsigned)__cvta_generic_to_shared(rb + c * 8192 + tid * 16);
            CP_ASYNC_16(d0, cb + c * 8192 + tid * 16);
            CP_ASYNC_16(d0 + 4096, cb + c * 8192 + tid * 16 + 4096);
            CP_COMMIT();
        }
    }

    // ---- per-thread DP metadata ----
    float A0 = NEGV, A1 = NEGV, A2 = NEGV, A3 = NEGV;
    float A4 = NEGV, A5 = NEGV, A6 = NEGV, A7 = NEGV, A8 = NEGV;
    float HE = NEGV, HO = NEGV;  // halo pair (warp1 lanes 0-7 meaningful)
    int e1 = 0, e3 = 0, e5 = 0, e7 = 0, eh = 0;
    bool k1 = false, k3 = false, k5 = false, k7 = false, kh = false;
    float vb = NEGV, vl = NEGV;
    bool own_b = false, own_l = false, own_b8 = false;
    int ob = 0, ol = 0;

    if (w < 2) {
        const int s0 = 256 * w + 8 * lane;    // base state of this thread
        const int u0 = s0 >> 1;               // 128w + 4*lane, 16B aligned
        const int* tg = targets + b * Uc;
        int4 t4 = *(const int4*)(tg + u0);    // targets for my 4 odd states
        e1 = t4.x; e3 = t4.y; e5 = t4.z; e7 = t4.w;
        k1 = (u0 > 0) && (e1 != tg[u0 - 1]);  // state s0+1: skip iff s>=3 && label!=prev
        k3 = (e3 != e1);
        k5 = (e5 != e3);
        k7 = (e7 != e5);
        if (w == 0 && lane == 0) A0 = 0.f;    // virtual alpha_{-1}[0]=0 => alpha_0[0..1]=em
        // halo metadata: states 240+2l (even), 241+2l (odd); odd label idx = 120+l
        {
            int ih = min(120 + lane, Uc - 1);
            eh = tg[ih];
            kh = (eh != tg[ih - 1]);
        }
        // snapshot ownership (idxb even in [256,512], idxl odd in [255,511])
        if ((idxb >> 3) == (s0 >> 3)) { own_b = true; ob = idxb & 7; }
        if ((idxl >> 3) == (s0 >> 3)) { own_l = true; ol = idxl & 7; }
        if (idxb == 512 && w == 1 && lane == 31) own_b8 = true;  // extra state
    }
    float accLZ = 0.f;

    for (int g = 0; g < ngroups; ++g) {
        CP_WAIT(PREF - 1);
        __syncthreads();  // chunk g visible; sh_halo[(g&1)] from prev group visible
        {
            int c = g + PREF;
            if (c < Tc / CHUNK) {
                const char* cb = (const char*)base + (size_t)c * 8192 + tid * 16;
                unsigned d0 = (unsigned)__cvta_generic_to_shared(
                    (char*)&ring[(c & (NCH - 1)) * CHUNK][0] + tid * 16);
                CP_ASYNC_16(d0, cb);
                CP_ASYNC_16(d0 + 4096, cb + 4096);
            }
            CP_COMMIT();
        }

        if (w < 2) {
            if (w == 1 && lane < 8) {
                HE = sh_halo[g & 1][2 * lane];
                HO = sh_halo[g & 1][2 * lane + 1];
            }
#pragma unroll
            for (int r = 0; r < 8; ++r) {
                const float* row = ring[(g & (NCH - 1)) * CHUNK + r];
                float emb = row[0];  // blank emission (broadcast)
                float P7 = __shfl_up_sync(0xffffffffu, A7, 1);   // alpha[s0-1]
                float hin = __shfl_sync(0xffffffffu, HO, 7);     // alpha[255] (warp0: NEGV)
                if (lane == 0) P7 = hin;
                if (w == 1) {  // halo recompute (uses OLD HE/HO)
                    float PO = __shfl_up_sync(0xffffffffu, HO, 1);
                    float emo = row[eh];
                    float HEn = fmaxf(HE, PO) + emb;
                    float HOn = fmaxf(fmaxf(HO, HE), kh ? PO : NEGV) + emo;
                    HE = HEn; HO = HOn;
                }
                float m1 = row[e1], m3 = row[e3], m5 = row[e5], m7 = row[e7];
                float n0 = fmaxf(A0, P7) + emb;
                float n1 = fmaxf(fmaxf(A1, A0), k1 ? P7 : NEGV) + m1;
                float n2 = fmaxf(A2, A1) + emb;
                float n3 = fmaxf(fmaxf(A3, A2), k3 ? A1 : NEGV) + m3;
                float n4 = fmaxf(A4, A3) + emb;
                float n5 = fmaxf(fmaxf(A5, A4), k5 ? A3 : NEGV) + m5;
                float n6 = fmaxf(A6, A5) + emb;
                float n7 = fmaxf(fmaxf(A7, A6), k7 ? A5 : NEGV) + m7;
                if (w == 1) A8 = fmaxf(A8, A7) + emb;  // state 512 (old A7 = alpha[511])
                A0 = n0; A1 = n1; A2 = n2; A3 = n3;
                A4 = n4; A5 = n5; A6 = n6; A7 = n7;
                int t = g * 8 + r;
                if (t == lenm1) {
                    if (own_b) vb = (ob & 4) ? ((ob & 2) ? A6 : A4) : ((ob & 2) ? A2 : A0);
                    if (own_b8) vb = A8;
                    if (own_l) vl = (ol & 4) ? ((ol & 2) ? A7 : A5) : ((ol & 2) ? A3 : A1);
                }
            }
            // publish alpha[240..255] for warp1's next-group halo
            if (w == 0 && lane >= 30) {
                float* dst = &sh_halo[(g + 1) & 1][(lane - 30) * 8];
                dst[0] = A0; dst[1] = A1; dst[2] = A2; dst[3] = A3;
                dst[4] = A4; dst[5] = A5; dst[6] = A6; dst[7] = A7;
            }
        } else {
            // helper warps 2..7: logsumexp of rows in this chunk
            for (int r = w - 2; r < 8; r += 6) {
                int t = g * 8 + r;
                if (t < len) {
                    const float4* r4 = (const float4*)ring[(g & (NCH - 1)) * CHUNK + r];
                    float4 x = r4[lane * 2], y = r4[lane * 2 + 1];
                    const float L2E = 1.4426950408889634f;
                    float s = exp2f(x.x * L2E) + exp2f(x.y * L2E) +
                              exp2f(x.z * L2E) + exp2f(x.w * L2E) +
                              exp2f(y.x * L2E) + exp2f(y.y * L2E) +
                              exp2f(y.z * L2E) + exp2f(y.w * L2E);
#pragma unroll
                    for (int o = 16; o; o >>= 1) s += __shfl_xor_sync(0xffffffffu, s, o);
                    accLZ += 0.69314718055994531f * log2f(s);
                }
            }
        }
    }
    __syncthreads();
    if (w >= 2 && lane == 0) sh_lz[w - 2] = accLZ;
    if (own_b || own_b8) sh_pair[0] = vb;
    if (own_l) sh_pair[1] = vl;
    __syncthreads();
    if (tid == 0) {
        float s = 0.f;
#pragma unroll
        for (int i = 0; i < 6; ++i) s += sh_lz[i];
        g_partial[b] = s - fmaxf(sh_pair[0], sh_pair[1]);
    }
}

// loss = sum_b partial[b] / sum_b len[b]   (fixed-order, deterministic)
__global__ void __launch_bounds__(32) finalize_kernel(const int* __restrict__ loglens,
                                                      float* __restrict__ out) {
    int lane = threadIdx.x;
    float num = g_partial[lane] + g_partial[lane + 32];
    float den = (float)loglens[lane] + (float)loglens[lane + 32];
#pragma unroll
    for (int o = 16; o; o >>= 1) {
        num += __shfl_down_sync(0xffffffffu, num, o);
        den += __shfl_down_sync(0xffffffffu, den, o);
    }
    if (lane == 0) out[0] = num / den;
}

extern "C" void kernel_launch(void* const* d_in, const int* in_sizes, int n_in,
                              void* d_out, int out_size) {
    const float* logits = (const float*)d_in[0];
    const int* targets = (const int*)d_in[1];
    const int* loglens = (const int*)d_in[2];
    const int* tgtlens = (const int*)d_in[3];
    float* out = (float*)d_out;

    dp_kernel<<<Bc, 256>>>(logits, targets, loglens, tgtlens);
    finalize_kernel<<<1, 32>>>(loglens, out);
}